// round 16
// baseline (speedup 1.0000x reference)
#include <cuda_runtime.h>
#include <cuda_fp16.h>
#include <math.h>
#include <stdint.h>

// Problem constants
#define BATCH 8
#define NPTS  8192
#define SPTS  2048
#define C1V   128
#define C2V   256
#define MROWS 65536
#define K1V   384
#define N1V   256
#define K2V   256
#define N2V   128
#define RPARTS 512            // one partial per 128-row GEMM tile

// Scratch (device globals: allocation-free)
__device__ __half g_Zh [(size_t)BATCH * SPTS * N1V];   // P2 @ W1b^T, fp16 (8 MB)
__device__ __half g_Y1h[(size_t)MROWS * N1V];          // Y1, fp16 (32 MB)
__device__ float  g_Y2 [(size_t)MROWS * N2V];
__device__ int   g_idx[MROWS * 3];
__device__ float g_wt [MROWS * 3];
__device__ float g_ps1[N1V * RPARTS], g_pq1[N1V * RPARTS];   // [col][rowtile]
__device__ float g_ps2[N2V * RPARTS], g_pq2[N2V * RPARTS];
__device__ float g_sc1[N1V], g_sh1[N1V];
__device__ float g_sc2[N2V], g_sh2[N2V];

// ---------------------------------------------------------------------------
// fp16 / mma helpers
// ---------------------------------------------------------------------------
__device__ __forceinline__ uint32_t smem_u32(const void* p) {
    uint32_t a;
    asm("{ .reg .u64 t; cvta.to.shared.u64 t, %1; cvt.u32.u64 %0, t; }"
        : "=r"(a) : "l"(p));
    return a;
}
// a = ah + al in fp16 (captures ~22 mantissa bits of a)
__device__ __forceinline__ void split_pack_fp16(float e, float o,
                                                uint32_t& h, uint32_t& l) {
    __half he = __float2half_rn(e);
    __half ho = __float2half_rn(o);
    float re = e - __half2float(he);
    float ro = o - __half2float(ho);
    __half2 hp = __halves2half2(he, ho);
    __half2 lp = __floats2half2_rn(re, ro);
    h = *(uint32_t*)&hp;
    l = *(uint32_t*)&lp;
}
__device__ __forceinline__ uint32_t pack_fp16(float e, float o) {
    __half2 p = __floats2half2_rn(e, o);
    return *(uint32_t*)&p;
}
__device__ __forceinline__ void mma16(float* c, const uint32_t* a,
                                      uint32_t b0, uint32_t b1) {
    asm volatile(
        "mma.sync.aligned.m16n8k16.row.col.f32.f16.f16.f32 "
        "{%0,%1,%2,%3}, {%4,%5,%6,%7}, {%8,%9}, {%0,%1,%2,%3};"
        : "+f"(c[0]), "+f"(c[1]), "+f"(c[2]), "+f"(c[3])
        : "r"(a[0]), "r"(a[1]), "r"(a[2]), "r"(a[3]), "r"(b0), "r"(b1));
}
__device__ __forceinline__ void ldsm_x4(uint32_t* r, uint32_t addr) {
    asm volatile(
        "ldmatrix.sync.aligned.m8n8.x4.shared.b16 {%0,%1,%2,%3}, [%4];"
        : "=r"(r[0]), "=r"(r[1]), "=r"(r[2]), "=r"(r[3]) : "r"(addr));
}

// ---------------------------------------------------------------------------
// Kernel 1: 3-NN + interpolation weights. 2 queries per thread (shared
// candidate broadcast + loop control); per-query scan order unchanged.
// ---------------------------------------------------------------------------
__global__ void nn3_kernel(const float* __restrict__ xyz1,
                           const float* __restrict__ xyz2)
{
    __shared__ float4 s2[SPTS];
    const int b = blockIdx.y;
    const float* x2 = xyz2 + (size_t)b * SPTS * 3;
    for (int i = threadIdx.x; i < SPTS; i += blockDim.x) {
        float x = x2[i*3+0], y = x2[i*3+1], z = x2[i*3+2];
        s2[i] = make_float4(x, y, z, 0.5f*(x*x + y*y + z*z));
    }
    __syncthreads();

    const int n0 = blockIdx.x * 512 + threadIdx.x;
    const int p0 = b * NPTS + n0;
    const int p1 = p0 + 256;

    const float ax0 = xyz1[(size_t)p0*3+0], ay0 = xyz1[(size_t)p0*3+1],
                az0 = xyz1[(size_t)p0*3+2];
    const float ax1 = xyz1[(size_t)p1*3+0], ay1 = xyz1[(size_t)p1*3+1],
                az1 = xyz1[(size_t)p1*3+2];
    const float an0 = ax0*ax0 + ay0*ay0 + az0*az0;
    const float an1 = ax1*ax1 + ay1*ay1 + az1*az1;

    float e00 = 1e30f, e01 = 1e30f, e02 = 1e30f;
    float e10 = 1e30f, e11 = 1e30f, e12 = 1e30f;
    int   j00 = 0, j01 = 0, j02 = 0;
    int   j10 = 0, j11 = 0, j12 = 0;
    #pragma unroll 4
    for (int s = 0; s < SPTS; s++) {
        float4 q = s2[s];
        float ea = fmaf(-ax0, q.x, fmaf(-ay0, q.y, fmaf(-az0, q.z, q.w)));
        float eb = fmaf(-ax1, q.x, fmaf(-ay1, q.y, fmaf(-az1, q.z, q.w)));
        if (ea < e02) {
            if (ea < e01) {
                if (ea < e00) { e02=e01; j02=j01; e01=e00; j01=j00; e00=ea; j00=s; }
                else          { e02=e01; j02=j01; e01=ea; j01=s; }
            } else            { e02=ea; j02=s; }
        }
        if (eb < e12) {
            if (eb < e11) {
                if (eb < e10) { e12=e11; j12=j11; e11=e10; j11=j10; e10=eb; j10=s; }
                else          { e12=e11; j12=j11; e11=eb; j11=s; }
            } else            { e12=eb; j12=s; }
        }
    }
    {
        float d0 = sqrtf(fmaxf(fmaf(2.0f, e00, an0), 0.0f));
        float d1 = sqrtf(fmaxf(fmaf(2.0f, e01, an0), 0.0f));
        float d2 = sqrtf(fmaxf(fmaf(2.0f, e02, an0), 0.0f));
        float r0 = 1.0f / (d0 + 1e-8f);
        float r1 = 1.0f / (d1 + 1e-8f);
        float r2 = 1.0f / (d2 + 1e-8f);
        float inv = 1.0f / (r0 + r1 + r2);
        g_wt[p0*3+0] = r0*inv; g_wt[p0*3+1] = r1*inv; g_wt[p0*3+2] = r2*inv;
        g_idx[p0*3+0] = j00;   g_idx[p0*3+1] = j01;   g_idx[p0*3+2] = j02;
    }
    {
        float d0 = sqrtf(fmaxf(fmaf(2.0f, e10, an1), 0.0f));
        float d1 = sqrtf(fmaxf(fmaf(2.0f, e11, an1), 0.0f));
        float d2 = sqrtf(fmaxf(fmaf(2.0f, e12, an1), 0.0f));
        float r0 = 1.0f / (d0 + 1e-8f);
        float r1 = 1.0f / (d1 + 1e-8f);
        float r2 = 1.0f / (d2 + 1e-8f);
        float inv = 1.0f / (r0 + r1 + r2);
        g_wt[p1*3+0] = r0*inv; g_wt[p1*3+1] = r1*inv; g_wt[p1*3+2] = r2*inv;
        g_idx[p1*3+0] = j10;   g_idx[p1*3+1] = j11;   g_idx[p1*3+2] = j12;
    }
}

// ---------------------------------------------------------------------------
// fp16x2 m16n8k16 GEMM (R15 pipeline), half-precision data plane:
//   Y[M,N] = op(A)[M,K] @ W[N,K]^T (+ bias) (+ interp_rows(Zsrc))
// y = (ah + al) * bh. CTA 128x128, BK=16, 8 warps, warp tile 32x64,
// double-buffered, 2 CTAs/SM, LDSM loads, term-major HMMA passes.
// TRANS_A : A is __half, converted to fp32 then relu(a*scale+shift)+split.
// FUSE_INTERP: epilogue gathers 3 rows of fp16 Zsrc (L2) per output row.
// OUT_HALF: Y stored as __half (packed half2 stores).
// psum==nullptr skips the fused BN-stats epilogue.
// ---------------------------------------------------------------------------
#define TROW_W 12                      // uint32 words per tile row
#define TILE_WRD (128 * TROW_W)
#define BUF_WRD (3 * TILE_WRD)         // Ah|Al|Bh per buffer

template<int KDIM, bool TRANS_A, bool FUSE_INTERP, bool OUT_HALF>
__global__ void __launch_bounds__(256, 2)
gemm_mma(const void* __restrict__ Ain, int lda,
         const float* __restrict__ W, int ldw,
         const float* __restrict__ bias,
         const float* __restrict__ aScale,
         const float* __restrict__ aShift,
         const __half* __restrict__ Zsrc,
         void* __restrict__ Yout,
         float* __restrict__ psum,
         float* __restrict__ psq,
         int N)
{
    extern __shared__ float sm[];
    float* sSc = sm;                    // [KDIM]
    float* sSh = sm + 384;              // [KDIM]
    uint32_t* tiles = (uint32_t*)(sm + 768);

    const int tid  = threadIdx.x;
    const int wid  = tid >> 5;
    const int lane = tid & 31;
    const int lg   = lane >> 2;
    const int lt   = lane & 3;
    const int wm   = (wid & 3) * 32;
    const int wn   = (wid >> 2) * 64;

    // ldmatrix per-lane addressing (bytes)
    const uint32_t tilesAddr = smem_u32(tiles);
    const int aRow = lane & 15;
    const int aOff = (lane >> 4) * 16;
    const int bRow = (lane & 7) + ((lane >> 4) << 3);
    const int bOff = ((lane >> 3) & 1) * 16;

    if (TRANS_A) {
        for (int i = tid; i < KDIM; i += 256) { sSc[i] = aScale[i]; sSh[i] = aShift[i]; }
        __syncthreads();
    }

    float acc[2][8][4];
    #pragma unroll
    for (int mt = 0; mt < 2; mt++)
        #pragma unroll
        for (int nt = 0; nt < 8; nt++)
            #pragma unroll
            for (int j = 0; j < 4; j++) acc[mt][nt][j] = 0.0f;

    const float*  Af32 = TRANS_A ? nullptr
                  : ((const float*)Ain + (size_t)blockIdx.y * 128 * lda);
    const __half* Af16 = TRANS_A
                  ? ((const __half*)Ain + (size_t)blockIdx.y * 128 * lda) : nullptr;
    const float* Wb = W + (size_t)blockIdx.x * 128 * ldw;

    const int r = tid >> 2;            // 0..63
    const int q = tid & 3;             // float4 slot within k16

    float4 av[2], wv[2];
    auto g_load = [&](int k0) {
        #pragma unroll
        for (int i = 0; i < 2; i++) {
            int rr = i*64 + r;
            float4 v;
            if (TRANS_A) {
                const uint2 hv = *(const uint2*)(Af16 + (size_t)rr*lda + k0 + q*4);
                const float2 f0 = __half22float2(*(const __half2*)&hv.x);
                const float2 f1 = __half22float2(*(const __half2*)&hv.y);
                v = make_float4(f0.x, f0.y, f1.x, f1.y);
                int kb = k0 + q*4;
                v.x = fmaxf(fmaf(v.x, sSc[kb+0], sSh[kb+0]), 0.0f);
                v.y = fmaxf(fmaf(v.y, sSc[kb+1], sSh[kb+1]), 0.0f);
                v.z = fmaxf(fmaf(v.z, sSc[kb+2], sSh[kb+2]), 0.0f);
                v.w = fmaxf(fmaf(v.w, sSc[kb+3], sSh[kb+3]), 0.0f);
            } else {
                v = *(const float4*)(Af32 + (size_t)rr*lda + k0 + q*4);
            }
            av[i] = v;
            wv[i] = *(const float4*)(Wb + (size_t)rr*ldw + k0 + q*4);
        }
    };
    auto s_store = [&](int buf) {
        uint32_t* base = tiles + buf * BUF_WRD;
        #pragma unroll
        for (int i = 0; i < 2; i++) {
            const int rr = i*64 + r;
            const int wo = rr * TROW_W + q*2;
            uint32_t h0, l0, h1, l1;
            split_pack_fp16(av[i].x, av[i].y, h0, l0);
            split_pack_fp16(av[i].z, av[i].w, h1, l1);
            *(uint2*)(base + wo)              = make_uint2(h0, h1);  // Ah
            *(uint2*)(base + TILE_WRD + wo)   = make_uint2(l0, l1);  // Al
            const uint32_t bh0 = pack_fp16(wv[i].x, wv[i].y);
            const uint32_t bh1 = pack_fp16(wv[i].z, wv[i].w);
            *(uint2*)(base + 2*TILE_WRD + wo) = make_uint2(bh0, bh1); // Bh
        }
    };
    auto do_mma = [&](int buf) {
        const uint32_t tb = tilesAddr + buf * (BUF_WRD * 4);
        uint32_t ahr[2][4], alr[2][4];
        #pragma unroll
        for (int mt = 0; mt < 2; mt++) {
            const uint32_t ad = tb + (uint32_t)((wm + mt*16 + aRow) * TROW_W) * 4 + aOff;
            ldsm_x4(ahr[mt], ad);
            ldsm_x4(alr[mt], ad + TILE_WRD * 4);
        }
        #pragma unroll
        for (int half = 0; half < 2; half++) {
            uint32_t bh[2][4];
            #pragma unroll
            for (int g = 0; g < 2; g++) {
                const int ntp = half*2 + g;
                const uint32_t bd = tb + 2*TILE_WRD*4
                    + (uint32_t)((wn + ntp*16 + bRow) * TROW_W) * 4 + bOff;
                ldsm_x4(bh[g], bd);
            }
            #pragma unroll
            for (int g = 0; g < 2; g++)
                #pragma unroll
                for (int s = 0; s < 2; s++)
                    #pragma unroll
                    for (int mt = 0; mt < 2; mt++)
                        mma16(acc[mt][half*4 + g*2 + s], ahr[mt],
                              bh[g][2*s], bh[g][2*s+1]);
            #pragma unroll
            for (int g = 0; g < 2; g++)
                #pragma unroll
                for (int s = 0; s < 2; s++)
                    #pragma unroll
                    for (int mt = 0; mt < 2; mt++)
                        mma16(acc[mt][half*4 + g*2 + s], alr[mt],
                              bh[g][2*s], bh[g][2*s+1]);
        }
    };

    const int KT = KDIM / 16;
    g_load(0);
    s_store(0);
    __syncthreads();
    for (int kt = 0; kt < KT; kt++) {
        if (kt + 1 < KT) g_load((kt + 1) * 16);
        do_mma(kt & 1);
        if (kt + 1 < KT) {
            s_store((kt + 1) & 1);
            __syncthreads();
        }
    }

    // ---- Fused interp: acc += w0*Z[i0] + w1*Z[i1] + w2*Z[i2] (fp16 L2 gathers)
    if (FUSE_INTERP) {
        #pragma unroll
        for (int mt = 0; mt < 2; mt++) {
            #pragma unroll
            for (int rh = 0; rh < 2; rh++) {
                const int row = blockIdx.y*128 + wm + mt*16 + rh*8 + lg;
                const int b = row >> 13;
                const int i0 = g_idx[row*3+0];
                const int i1 = g_idx[row*3+1];
                const int i2 = g_idx[row*3+2];
                const float w0 = g_wt[row*3+0];
                const float w1 = g_wt[row*3+1];
                const float w2 = g_wt[row*3+2];
                const __half* z0 = Zsrc + ((size_t)b*SPTS + i0) * N;
                const __half* z1 = Zsrc + ((size_t)b*SPTS + i1) * N;
                const __half* z2 = Zsrc + ((size_t)b*SPTS + i2) * N;
                #pragma unroll
                for (int nt = 0; nt < 8; nt++) {
                    const int col = blockIdx.x*128 + wn + nt*8 + 2*lt;
                    const float2 va = __half22float2(*(const __half2*)(z0 + col));
                    const float2 vb = __half22float2(*(const __half2*)(z1 + col));
                    const float2 vc = __half22float2(*(const __half2*)(z2 + col));
                    acc[mt][nt][rh*2+0] += w0*va.x + w1*vb.x + w2*vc.x;
                    acc[mt][nt][rh*2+1] += w0*va.y + w1*vb.y + w2*vc.y;
                }
            }
        }
    }

    // ---- Epilogue: (+bias), store Y, optional fused BN partials
    #pragma unroll
    for (int nt = 0; nt < 8; nt++) {
        const int col = blockIdx.x*128 + wn + nt*8 + 2*lt;
        const float b0 = bias ? __ldg(&bias[col])   : 0.0f;
        const float b1 = bias ? __ldg(&bias[col+1]) : 0.0f;
        #pragma unroll
        for (int mt = 0; mt < 2; mt++) {
            const int row0 = blockIdx.y*128 + wm + mt*16 + lg;
            acc[mt][nt][0] += b0; acc[mt][nt][1] += b1;
            acc[mt][nt][2] += b0; acc[mt][nt][3] += b1;
            if (OUT_HALF) {
                __half* Yh = (__half*)Yout;
                *(uint32_t*)(Yh + (size_t)row0 * N + col) =
                    pack_fp16(acc[mt][nt][0], acc[mt][nt][1]);
                *(uint32_t*)(Yh + (size_t)(row0+8) * N + col) =
                    pack_fp16(acc[mt][nt][2], acc[mt][nt][3]);
            } else {
                float* Yf = (float*)Yout;
                *(float2*)(Yf + (size_t)row0 * N + col) =
                    make_float2(acc[mt][nt][0], acc[mt][nt][1]);
                *(float2*)(Yf + (size_t)(row0+8) * N + col) =
                    make_float2(acc[mt][nt][2], acc[mt][nt][3]);
            }
        }
    }

    if (psum != nullptr) {                // uniform branch
        __syncthreads();                  // reuse tiles as reduction space
        float* srs = (float*)tiles;
        float* srq = (float*)tiles + 512;
        #pragma unroll
        for (int nt = 0; nt < 8; nt++) {
            float sA = acc[0][nt][0] + acc[0][nt][2] + acc[1][nt][0] + acc[1][nt][2];
            float sB = acc[0][nt][1] + acc[0][nt][3] + acc[1][nt][1] + acc[1][nt][3];
            float qA = acc[0][nt][0]*acc[0][nt][0] + acc[0][nt][2]*acc[0][nt][2]
                     + acc[1][nt][0]*acc[1][nt][0] + acc[1][nt][2]*acc[1][nt][2];
            float qB = acc[0][nt][1]*acc[0][nt][1] + acc[0][nt][3]*acc[0][nt][3]
                     + acc[1][nt][1]*acc[1][nt][1] + acc[1][nt][3]*acc[1][nt][3];
            #pragma unroll
            for (int o = 4; o <= 16; o <<= 1) {
                sA += __shfl_xor_sync(0xFFFFFFFFu, sA, o);
                sB += __shfl_xor_sync(0xFFFFFFFFu, sB, o);
                qA += __shfl_xor_sync(0xFFFFFFFFu, qA, o);
                qB += __shfl_xor_sync(0xFFFFFFFFu, qB, o);
            }
            if (lane < 4) {
                srs[wid*64 + nt*8 + lane*2 + 0] = sA;
                srs[wid*64 + nt*8 + lane*2 + 1] = sB;
                srq[wid*64 + nt*8 + lane*2 + 0] = qA;
                srq[wid*64 + nt*8 + lane*2 + 1] = qB;
            }
        }
        __syncthreads();
        if (tid < 128) {
            const int w0 = tid >> 6, cc = tid & 63;
            float s = 0.0f, qq = 0.0f;
            #pragma unroll
            for (int k = 0; k < 4; k++) {
                s  += srs[(w0*4 + k)*64 + cc];
                qq += srq[(w0*4 + k)*64 + cc];
            }
            // transposed: [col][rowtile] -> contiguous per-channel reduction
            const size_t o = (size_t)(blockIdx.x*128 + tid) * RPARTS + blockIdx.y;
            psum[o] = s;
            psq [o] = qq;
        }
    }
}

// ---------------------------------------------------------------------------
// BN stats stage 2: one block per channel; 512 contiguous partials.
// ---------------------------------------------------------------------------
__global__ void bn_stats2(const float* __restrict__ ps, const float* __restrict__ pq,
                          const float* __restrict__ g,
                          const float* __restrict__ beta,
                          float* __restrict__ scale, float* __restrict__ shift)
{
    __shared__ float ss[4], sq[4];
    const int c = blockIdx.x, tid = threadIdx.x;   // 128 threads
    float4 v = ((const float4*)(ps + (size_t)c * RPARTS))[tid];
    float4 w = ((const float4*)(pq + (size_t)c * RPARTS))[tid];
    float s = (v.x + v.y) + (v.z + v.w);
    float q = (w.x + w.y) + (w.z + w.w);
    #pragma unroll
    for (int o = 16; o >= 1; o >>= 1) {
        s += __shfl_down_sync(0xFFFFFFFFu, s, o);
        q += __shfl_down_sync(0xFFFFFFFFu, q, o);
    }
    if ((tid & 31) == 0) { ss[tid >> 5] = s; sq[tid >> 5] = q; }
    __syncthreads();
    if (tid == 0) {
        double S = ((double)ss[0] + (double)ss[1]) + ((double)ss[2] + (double)ss[3]);
        double Q = ((double)sq[0] + (double)sq[1]) + ((double)sq[2] + (double)sq[3]);
        double mu  = S / (double)MROWS;
        double var = Q / (double)MROWS - mu * mu;
        float sc = g[c] / sqrtf((float)var + 1e-5f);
        scale[c] = sc;
        shift[c] = beta[c] - (float)mu * sc;
    }
}

// ---------------------------------------------------------------------------
// Final: out = relu(Y2 * scale2 + shift2)
// ---------------------------------------------------------------------------
__global__ void bn_relu_out_kernel(const float* __restrict__ Y,
                                   float* __restrict__ out)
{
    int i = blockIdx.x * blockDim.x + threadIdx.x;
    const float4 v = ((const float4*)Y)[i];
    int c = (i * 4) & (N2V - 1);
    float4 o;
    o.x = fmaxf(fmaf(v.x, g_sc2[c+0], g_sh2[c+0]), 0.0f);
    o.y = fmaxf(fmaf(v.y, g_sc2[c+1], g_sh2[c+1]), 0.0f);
    o.z = fmaxf(fmaf(v.z, g_sc2[c+2], g_sh2[c+2]), 0.0f);
    o.w = fmaxf(fmaf(v.w, g_sc2[c+3], g_sh2[c+3]), 0.0f);
    ((float4*)out)[i] = o;
}

// ---------------------------------------------------------------------------
// Launcher (graph-capturable)
// ---------------------------------------------------------------------------
extern "C" void kernel_launch(void* const* d_in, const int* in_sizes, int n_in,
                              void* d_out, int out_size)
{
    const float* xyz1    = (const float*)d_in[0];
    const float* xyz2    = (const float*)d_in[1];
    const float* points1 = (const float*)d_in[2];
    const float* points2 = (const float*)d_in[3];
    const float* w1      = (const float*)d_in[4];
    const float* b1      = (const float*)d_in[5];
    const float* g1      = (const float*)d_in[6];
    const float* beta1   = (const float*)d_in[7];
    const float* w2      = (const float*)d_in[8];
    const float* b2      = (const float*)d_in[9];
    const float* g2      = (const float*)d_in[10];
    const float* beta2   = (const float*)d_in[11];
    float* out = (float*)d_out;

    __half *pZh, *pY1h;
    float *pY2, *pps1, *ppq1, *pps2, *ppq2, *psc1, *psh1, *psc2, *psh2;
    cudaGetSymbolAddress((void**)&pZh,  g_Zh);
    cudaGetSymbolAddress((void**)&pY1h, g_Y1h);
    cudaGetSymbolAddress((void**)&pY2,  g_Y2);
    cudaGetSymbolAddress((void**)&pps1, g_ps1);
    cudaGetSymbolAddress((void**)&ppq1, g_pq1);
    cudaGetSymbolAddress((void**)&pps2, g_ps2);
    cudaGetSymbolAddress((void**)&ppq2, g_pq2);
    cudaGetSymbolAddress((void**)&psc1, g_sc1);
    cudaGetSymbolAddress((void**)&psh1, g_sh1);
    cudaGetSymbolAddress((void**)&psc2, g_sc2);
    cudaGetSymbolAddress((void**)&psh2, g_sh2);

    const int SMEM = 768*4 + 2 * BUF_WRD * 4;    // 39936 B
    cudaFuncSetAttribute(gemm_mma<C2V, false, false, true>,
                         cudaFuncAttributeMaxDynamicSharedMemorySize, SMEM);
    cudaFuncSetAttribute(gemm_mma<C1V, false, true, true>,
                         cudaFuncAttributeMaxDynamicSharedMemorySize, SMEM);
    cudaFuncSetAttribute(gemm_mma<K2V, true, false, false>,
                         cudaFuncAttributeMaxDynamicSharedMemorySize, SMEM);

    // 1) 3-NN weights (2 queries per thread)
    nn3_kernel<<<dim3(NPTS/512, BATCH), 256>>>(xyz1, xyz2);
    // 2) Z = P2 @ W1b^T  -> fp16  (16384 x 256, K=256; W1b = w1[:,128:384])
    gemm_mma<C2V, false, false, true><<<dim3(N1V/128, (BATCH*SPTS)/128), 256, SMEM>>>(
        points2, C2V, w1 + C1V, K1V, nullptr, nullptr, nullptr, nullptr,
        pZh, nullptr, nullptr, N1V);
    // 3) Y1 = P1 @ W1a^T + interp(Zh) + b1 -> fp16  (K=128; interp fused)
    gemm_mma<C1V, false, true, true><<<dim3(N1V/128, MROWS/128), 256, SMEM>>>(
        points1, C1V, w1, K1V, b1, nullptr, nullptr, pZh,
        pY1h, pps1, ppq1, N1V);
    bn_stats2<<<N1V, 128>>>(pps1, ppq1, g1, beta1, psc1, psh1);
    // 4) Y2 = relu(BN1(Y1h)) @ W2^T + b2 -> fp32
    gemm_mma<K2V, true, false, false><<<dim3(N2V/128, MROWS/128), 256, SMEM>>>(
        pY1h, K2V, w2, K2V, b2, psc1, psh1, nullptr,
        pY2, pps2, ppq2, N2V);
    bn_stats2<<<N2V, 128>>>(pps2, ppq2, g2, beta2, psc2, psh2);
    // 5) out = relu(BN2(Y2))
    bn_relu_out_kernel<<<(MROWS * N2V / 4) / 256, 256>>>(pY2, out);
}

// round 17
// speedup vs baseline: 1.2504x; 1.2504x over previous
#include <cuda_runtime.h>
#include <cuda_fp16.h>
#include <math.h>
#include <stdint.h>

// Problem constants
#define BATCH 8
#define NPTS  8192
#define SPTS  2048
#define C1V   128
#define C2V   256
#define MROWS 65536
#define K1V   384
#define N1V   256
#define K2V   256
#define N2V   128
#define RPARTS 512            // one partial per 128-row GEMM tile

// Scratch (device globals: allocation-free)
__device__ __half g_Zh[(size_t)BATCH * SPTS * N1V];  // P2 @ W1b^T, fp16 (8 MB, L2)
__device__ float g_Y1[(size_t)MROWS * N1V];
__device__ float g_Y2[(size_t)MROWS * N2V];
__device__ int   g_idx[MROWS * 3];
__device__ float g_wt [MROWS * 3];
__device__ float g_ps1[N1V * RPARTS], g_pq1[N1V * RPARTS];   // [col][rowtile]
__device__ float g_ps2[N2V * RPARTS], g_pq2[N2V * RPARTS];
__device__ float g_sc1[N1V], g_sh1[N1V];
__device__ float g_sc2[N2V], g_sh2[N2V];

// ---------------------------------------------------------------------------
// fp16 / mma helpers
// ---------------------------------------------------------------------------
__device__ __forceinline__ uint32_t smem_u32(const void* p) {
    uint32_t a;
    asm("{ .reg .u64 t; cvta.to.shared.u64 t, %1; cvt.u32.u64 %0, t; }"
        : "=r"(a) : "l"(p));
    return a;
}
// a = ah + al in fp16 (captures ~22 mantissa bits of a)
__device__ __forceinline__ void split_pack_fp16(float e, float o,
                                                uint32_t& h, uint32_t& l) {
    __half he = __float2half_rn(e);
    __half ho = __float2half_rn(o);
    float re = e - __half2float(he);
    float ro = o - __half2float(ho);
    __half2 hp = __halves2half2(he, ho);
    __half2 lp = __floats2half2_rn(re, ro);
    h = *(uint32_t*)&hp;
    l = *(uint32_t*)&lp;
}
__device__ __forceinline__ uint32_t pack_fp16(float e, float o) {
    __half2 p = __floats2half2_rn(e, o);
    return *(uint32_t*)&p;
}
__device__ __forceinline__ void mma16(float* c, const uint32_t* a,
                                      uint32_t b0, uint32_t b1) {
    asm volatile(
        "mma.sync.aligned.m16n8k16.row.col.f32.f16.f16.f32 "
        "{%0,%1,%2,%3}, {%4,%5,%6,%7}, {%8,%9}, {%0,%1,%2,%3};"
        : "+f"(c[0]), "+f"(c[1]), "+f"(c[2]), "+f"(c[3])
        : "r"(a[0]), "r"(a[1]), "r"(a[2]), "r"(a[3]), "r"(b0), "r"(b1));
}
__device__ __forceinline__ void ldsm_x4(uint32_t* r, uint32_t addr) {
    asm volatile(
        "ldmatrix.sync.aligned.m8n8.x4.shared.b16 {%0,%1,%2,%3}, [%4];"
        : "=r"(r[0]), "=r"(r[1]), "=r"(r[2]), "=r"(r[3]) : "r"(addr));
}

// ---------------------------------------------------------------------------
// Kernel 1: 3-NN + interpolation weights (proven R15 version, 1 query/thread)
// ---------------------------------------------------------------------------
__global__ void nn3_kernel(const float* __restrict__ xyz1,
                           const float* __restrict__ xyz2)
{
    __shared__ float4 s2[SPTS];
    const int b = blockIdx.y;
    const float* x2 = xyz2 + (size_t)b * SPTS * 3;
    for (int i = threadIdx.x; i < SPTS; i += blockDim.x) {
        float x = x2[i*3+0], y = x2[i*3+1], z = x2[i*3+2];
        s2[i] = make_float4(x, y, z, 0.5f*(x*x + y*y + z*z));
    }
    __syncthreads();

    const int n = blockIdx.x * blockDim.x + threadIdx.x;
    const int p = b * NPTS + n;
    const float ax = xyz1[(size_t)p*3+0];
    const float ay = xyz1[(size_t)p*3+1];
    const float az = xyz1[(size_t)p*3+2];
    const float an = ax*ax + ay*ay + az*az;

    float e0 = 1e30f, e1 = 1e30f, e2 = 1e30f;
    int   j0 = 0,     j1 = 0,     j2 = 0;
    #pragma unroll 8
    for (int s = 0; s < SPTS; s++) {
        float4 q = s2[s];
        float ee = fmaf(-ax, q.x, fmaf(-ay, q.y, fmaf(-az, q.z, q.w)));
        if (ee < e2) {
            if (ee < e1) {
                if (ee < e0) { e2=e1; j2=j1; e1=e0; j1=j0; e0=ee; j0=s; }
                else         { e2=e1; j2=j1; e1=ee; j1=s; }
            } else           { e2=ee; j2=s; }
        }
    }
    float d0 = sqrtf(fmaxf(fmaf(2.0f, e0, an), 0.0f));
    float d1 = sqrtf(fmaxf(fmaf(2.0f, e1, an), 0.0f));
    float d2 = sqrtf(fmaxf(fmaf(2.0f, e2, an), 0.0f));
    float r0 = 1.0f / (d0 + 1e-8f);
    float r1 = 1.0f / (d1 + 1e-8f);
    float r2 = 1.0f / (d2 + 1e-8f);
    float inv = 1.0f / (r0 + r1 + r2);
    g_wt[p*3+0] = r0*inv; g_wt[p*3+1] = r1*inv; g_wt[p*3+2] = r2*inv;
    g_idx[p*3+0] = j0;    g_idx[p*3+1] = j1;    g_idx[p*3+2] = j2;
}

// ---------------------------------------------------------------------------
// fp16x2 m16n8k16 GEMM (R15 pipeline) with row strides + FUSED INTERP:
//   Y[M,N] = op(A)[M,K] @ W[N,K]^T (+ bias) (+ interp_rows(Zsrc))
// y = (ah + al) * bh. CTA 128x128, BK=16, 8 warps, warp tile 32x64,
// double-buffered, 2 CTAs/SM, LDSM loads, term-major HMMA passes.
// A is always fp32 (LDG.128 path — proven); TRANS_A fuses the previous BN's
// relu(a*scale+shift) into the A load.
// FUSE_INTERP: epilogue gathers 3 fp16 rows of Zsrc (L2-resident) per output
// row and adds w0*z0+w1*z1+w2*z2.
// OUT_HALF: Y stored as packed half2 (Z GEMM); else fp32 float2.
// psum==nullptr skips the fused BN-stats epilogue.
// ---------------------------------------------------------------------------
#define TROW_W 12                      // uint32 words per tile row
#define TILE_WRD (128 * TROW_W)
#define BUF_WRD (3 * TILE_WRD)         // Ah|Al|Bh per buffer

template<int KDIM, bool TRANS_A, bool FUSE_INTERP, bool OUT_HALF>
__global__ void __launch_bounds__(256, 2)
gemm_mma(const float* __restrict__ A, int lda,
         const float* __restrict__ W, int ldw,
         const float* __restrict__ bias,
         const float* __restrict__ aScale,
         const float* __restrict__ aShift,
         const __half* __restrict__ Zsrc,
         void* __restrict__ Yout,
         float* __restrict__ psum,
         float* __restrict__ psq,
         int N)
{
    extern __shared__ float sm[];
    float* sSc = sm;                    // [KDIM]
    float* sSh = sm + 384;              // [KDIM]
    uint32_t* tiles = (uint32_t*)(sm + 768);

    const int tid  = threadIdx.x;
    const int wid  = tid >> 5;
    const int lane = tid & 31;
    const int lg   = lane >> 2;
    const int lt   = lane & 3;
    const int wm   = (wid & 3) * 32;
    const int wn   = (wid >> 2) * 64;

    // ldmatrix per-lane addressing (bytes)
    const uint32_t tilesAddr = smem_u32(tiles);
    const int aRow = lane & 15;
    const int aOff = (lane >> 4) * 16;
    const int bRow = (lane & 7) + ((lane >> 4) << 3);
    const int bOff = ((lane >> 3) & 1) * 16;

    if (TRANS_A) {
        for (int i = tid; i < KDIM; i += 256) { sSc[i] = aScale[i]; sSh[i] = aShift[i]; }
        __syncthreads();
    }

    float acc[2][8][4];
    #pragma unroll
    for (int mt = 0; mt < 2; mt++)
        #pragma unroll
        for (int nt = 0; nt < 8; nt++)
            #pragma unroll
            for (int j = 0; j < 4; j++) acc[mt][nt][j] = 0.0f;

    const float* Ab = A + (size_t)blockIdx.y * 128 * lda;
    const float* Wb = W + (size_t)blockIdx.x * 128 * ldw;

    const int r = tid >> 2;            // 0..63
    const int q = tid & 3;             // float4 slot within k16

    float4 av[2], wv[2];
    auto g_load = [&](int k0) {
        #pragma unroll
        for (int i = 0; i < 2; i++) {
            int rr = i*64 + r;
            float4 v = *(const float4*)(Ab + (size_t)rr*lda + k0 + q*4);
            if (TRANS_A) {
                int kb = k0 + q*4;
                v.x = fmaxf(fmaf(v.x, sSc[kb+0], sSh[kb+0]), 0.0f);
                v.y = fmaxf(fmaf(v.y, sSc[kb+1], sSh[kb+1]), 0.0f);
                v.z = fmaxf(fmaf(v.z, sSc[kb+2], sSh[kb+2]), 0.0f);
                v.w = fmaxf(fmaf(v.w, sSc[kb+3], sSh[kb+3]), 0.0f);
            }
            av[i] = v;
            wv[i] = *(const float4*)(Wb + (size_t)rr*ldw + k0 + q*4);
        }
    };
    auto s_store = [&](int buf) {
        uint32_t* base = tiles + buf * BUF_WRD;
        #pragma unroll
        for (int i = 0; i < 2; i++) {
            const int rr = i*64 + r;
            const int wo = rr * TROW_W + q*2;
            uint32_t h0, l0, h1, l1;
            split_pack_fp16(av[i].x, av[i].y, h0, l0);
            split_pack_fp16(av[i].z, av[i].w, h1, l1);
            *(uint2*)(base + wo)              = make_uint2(h0, h1);  // Ah
            *(uint2*)(base + TILE_WRD + wo)   = make_uint2(l0, l1);  // Al
            const uint32_t bh0 = pack_fp16(wv[i].x, wv[i].y);
            const uint32_t bh1 = pack_fp16(wv[i].z, wv[i].w);
            *(uint2*)(base + 2*TILE_WRD + wo) = make_uint2(bh0, bh1); // Bh
        }
    };
    auto do_mma = [&](int buf) {
        const uint32_t tb = tilesAddr + buf * (BUF_WRD * 4);
        uint32_t ahr[2][4], alr[2][4];
        #pragma unroll
        for (int mt = 0; mt < 2; mt++) {
            const uint32_t ad = tb + (uint32_t)((wm + mt*16 + aRow) * TROW_W) * 4 + aOff;
            ldsm_x4(ahr[mt], ad);
            ldsm_x4(alr[mt], ad + TILE_WRD * 4);
        }
        #pragma unroll
        for (int half = 0; half < 2; half++) {
            uint32_t bh[2][4];
            #pragma unroll
            for (int g = 0; g < 2; g++) {
                const int ntp = half*2 + g;
                const uint32_t bd = tb + 2*TILE_WRD*4
                    + (uint32_t)((wn + ntp*16 + bRow) * TROW_W) * 4 + bOff;
                ldsm_x4(bh[g], bd);
            }
            #pragma unroll
            for (int g = 0; g < 2; g++)
                #pragma unroll
                for (int s = 0; s < 2; s++)
                    #pragma unroll
                    for (int mt = 0; mt < 2; mt++)
                        mma16(acc[mt][half*4 + g*2 + s], ahr[mt],
                              bh[g][2*s], bh[g][2*s+1]);
            #pragma unroll
            for (int g = 0; g < 2; g++)
                #pragma unroll
                for (int s = 0; s < 2; s++)
                    #pragma unroll
                    for (int mt = 0; mt < 2; mt++)
                        mma16(acc[mt][half*4 + g*2 + s], alr[mt],
                              bh[g][2*s], bh[g][2*s+1]);
        }
    };

    const int KT = KDIM / 16;
    g_load(0);
    s_store(0);
    __syncthreads();
    for (int kt = 0; kt < KT; kt++) {
        if (kt + 1 < KT) g_load((kt + 1) * 16);
        do_mma(kt & 1);
        if (kt + 1 < KT) {
            s_store((kt + 1) & 1);
            __syncthreads();
        }
    }

    // ---- Fused interp: acc += w0*Z[i0] + w1*Z[i1] + w2*Z[i2] (fp16 L2 gathers)
    if (FUSE_INTERP) {
        #pragma unroll
        for (int mt = 0; mt < 2; mt++) {
            #pragma unroll
            for (int rh = 0; rh < 2; rh++) {
                const int row = blockIdx.y*128 + wm + mt*16 + rh*8 + lg;
                const int b = row >> 13;
                const int i0 = g_idx[row*3+0];
                const int i1 = g_idx[row*3+1];
                const int i2 = g_idx[row*3+2];
                const float w0 = g_wt[row*3+0];
                const float w1 = g_wt[row*3+1];
                const float w2 = g_wt[row*3+2];
                const __half* z0 = Zsrc + ((size_t)b*SPTS + i0) * N;
                const __half* z1 = Zsrc + ((size_t)b*SPTS + i1) * N;
                const __half* z2 = Zsrc + ((size_t)b*SPTS + i2) * N;
                #pragma unroll
                for (int nt = 0; nt < 8; nt++) {
                    const int col = blockIdx.x*128 + wn + nt*8 + 2*lt;
                    const float2 va = __half22float2(*(const __half2*)(z0 + col));
                    const float2 vb = __half22float2(*(const __half2*)(z1 + col));
                    const float2 vc = __half22float2(*(const __half2*)(z2 + col));
                    acc[mt][nt][rh*2+0] += w0*va.x + w1*vb.x + w2*vc.x;
                    acc[mt][nt][rh*2+1] += w0*va.y + w1*vb.y + w2*vc.y;
                }
            }
        }
    }

    // ---- Epilogue: (+bias), store Y, optional fused BN partials
    #pragma unroll
    for (int nt = 0; nt < 8; nt++) {
        const int col = blockIdx.x*128 + wn + nt*8 + 2*lt;
        const float b0 = bias ? __ldg(&bias[col])   : 0.0f;
        const float b1 = bias ? __ldg(&bias[col+1]) : 0.0f;
        #pragma unroll
        for (int mt = 0; mt < 2; mt++) {
            const int row0 = blockIdx.y*128 + wm + mt*16 + lg;
            acc[mt][nt][0] += b0; acc[mt][nt][1] += b1;
            acc[mt][nt][2] += b0; acc[mt][nt][3] += b1;
            if (OUT_HALF) {
                __half* Yh = (__half*)Yout;
                *(uint32_t*)(Yh + (size_t)row0 * N + col) =
                    pack_fp16(acc[mt][nt][0], acc[mt][nt][1]);
                *(uint32_t*)(Yh + (size_t)(row0+8) * N + col) =
                    pack_fp16(acc[mt][nt][2], acc[mt][nt][3]);
            } else {
                float* Yf = (float*)Yout;
                *(float2*)(Yf + (size_t)row0 * N + col) =
                    make_float2(acc[mt][nt][0], acc[mt][nt][1]);
                *(float2*)(Yf + (size_t)(row0+8) * N + col) =
                    make_float2(acc[mt][nt][2], acc[mt][nt][3]);
            }
        }
    }

    if (psum != nullptr) {                // uniform branch
        __syncthreads();                  // reuse tiles as reduction space
        float* srs = (float*)tiles;
        float* srq = (float*)tiles + 512;
        #pragma unroll
        for (int nt = 0; nt < 8; nt++) {
            float sA = acc[0][nt][0] + acc[0][nt][2] + acc[1][nt][0] + acc[1][nt][2];
            float sB = acc[0][nt][1] + acc[0][nt][3] + acc[1][nt][1] + acc[1][nt][3];
            float qA = acc[0][nt][0]*acc[0][nt][0] + acc[0][nt][2]*acc[0][nt][2]
                     + acc[1][nt][0]*acc[1][nt][0] + acc[1][nt][2]*acc[1][nt][2];
            float qB = acc[0][nt][1]*acc[0][nt][1] + acc[0][nt][3]*acc[0][nt][3]
                     + acc[1][nt][1]*acc[1][nt][1] + acc[1][nt][3]*acc[1][nt][3];
            #pragma unroll
            for (int o = 4; o <= 16; o <<= 1) {
                sA += __shfl_xor_sync(0xFFFFFFFFu, sA, o);
                sB += __shfl_xor_sync(0xFFFFFFFFu, sB, o);
                qA += __shfl_xor_sync(0xFFFFFFFFu, qA, o);
                qB += __shfl_xor_sync(0xFFFFFFFFu, qB, o);
            }
            if (lane < 4) {
                srs[wid*64 + nt*8 + lane*2 + 0] = sA;
                srs[wid*64 + nt*8 + lane*2 + 1] = sB;
                srq[wid*64 + nt*8 + lane*2 + 0] = qA;
                srq[wid*64 + nt*8 + lane*2 + 1] = qB;
            }
        }
        __syncthreads();
        if (tid < 128) {
            const int w0 = tid >> 6, cc = tid & 63;
            float s = 0.0f, qq = 0.0f;
            #pragma unroll
            for (int k = 0; k < 4; k++) {
                s  += srs[(w0*4 + k)*64 + cc];
                qq += srq[(w0*4 + k)*64 + cc];
            }
            // transposed: [col][rowtile] -> contiguous per-channel reduction
            const size_t o = (size_t)(blockIdx.x*128 + tid) * RPARTS + blockIdx.y;
            psum[o] = s;
            psq [o] = qq;
        }
    }
}

// ---------------------------------------------------------------------------
// BN stats stage 2: one block per channel; 512 contiguous partials.
// ---------------------------------------------------------------------------
__global__ void bn_stats2(const float* __restrict__ ps, const float* __restrict__ pq,
                          const float* __restrict__ g,
                          const float* __restrict__ beta,
                          float* __restrict__ scale, float* __restrict__ shift)
{
    __shared__ float ss[4], sq[4];
    const int c = blockIdx.x, tid = threadIdx.x;   // 128 threads
    float4 v = ((const float4*)(ps + (size_t)c * RPARTS))[tid];
    float4 w = ((const float4*)(pq + (size_t)c * RPARTS))[tid];
    float s = (v.x + v.y) + (v.z + v.w);
    float q = (w.x + w.y) + (w.z + w.w);
    #pragma unroll
    for (int o = 16; o >= 1; o >>= 1) {
        s += __shfl_down_sync(0xFFFFFFFFu, s, o);
        q += __shfl_down_sync(0xFFFFFFFFu, q, o);
    }
    if ((tid & 31) == 0) { ss[tid >> 5] = s; sq[tid >> 5] = q; }
    __syncthreads();
    if (tid == 0) {
        double S = ((double)ss[0] + (double)ss[1]) + ((double)ss[2] + (double)ss[3]);
        double Q = ((double)sq[0] + (double)sq[1]) + ((double)sq[2] + (double)sq[3]);
        double mu  = S / (double)MROWS;
        double var = Q / (double)MROWS - mu * mu;
        float sc = g[c] / sqrtf((float)var + 1e-5f);
        scale[c] = sc;
        shift[c] = beta[c] - (float)mu * sc;
    }
}

// ---------------------------------------------------------------------------
// Final: out = relu(Y2 * scale2 + shift2)
// ---------------------------------------------------------------------------
__global__ void bn_relu_out_kernel(const float* __restrict__ Y,
                                   float* __restrict__ out)
{
    int i = blockIdx.x * blockDim.x + threadIdx.x;
    const float4 v = ((const float4*)Y)[i];
    int c = (i * 4) & (N2V - 1);
    float4 o;
    o.x = fmaxf(fmaf(v.x, g_sc2[c+0], g_sh2[c+0]), 0.0f);
    o.y = fmaxf(fmaf(v.y, g_sc2[c+1], g_sh2[c+1]), 0.0f);
    o.z = fmaxf(fmaf(v.z, g_sc2[c+2], g_sh2[c+2]), 0.0f);
    o.w = fmaxf(fmaf(v.w, g_sc2[c+3], g_sh2[c+3]), 0.0f);
    ((float4*)out)[i] = o;
}

// ---------------------------------------------------------------------------
// Launcher (graph-capturable)
// ---------------------------------------------------------------------------
extern "C" void kernel_launch(void* const* d_in, const int* in_sizes, int n_in,
                              void* d_out, int out_size)
{
    const float* xyz1    = (const float*)d_in[0];
    const float* xyz2    = (const float*)d_in[1];
    const float* points1 = (const float*)d_in[2];
    const float* points2 = (const float*)d_in[3];
    const float* w1      = (const float*)d_in[4];
    const float* b1      = (const float*)d_in[5];
    const float* g1      = (const float*)d_in[6];
    const float* beta1   = (const float*)d_in[7];
    const float* w2      = (const float*)d_in[8];
    const float* b2      = (const float*)d_in[9];
    const float* g2      = (const float*)d_in[10];
    const float* beta2   = (const float*)d_in[11];
    float* out = (float*)d_out;

    __half *pZh;
    float *pY1, *pY2, *pps1, *ppq1, *pps2, *ppq2, *psc1, *psh1, *psc2, *psh2;
    cudaGetSymbolAddress((void**)&pZh,  g_Zh);
    cudaGetSymbolAddress((void**)&pY1,  g_Y1);
    cudaGetSymbolAddress((void**)&pY2,  g_Y2);
    cudaGetSymbolAddress((void**)&pps1, g_ps1);
    cudaGetSymbolAddress((void**)&ppq1, g_pq1);
    cudaGetSymbolAddress((void**)&pps2, g_ps2);
    cudaGetSymbolAddress((void**)&ppq2, g_pq2);
    cudaGetSymbolAddress((void**)&psc1, g_sc1);
    cudaGetSymbolAddress((void**)&psh1, g_sh1);
    cudaGetSymbolAddress((void**)&psc2, g_sc2);
    cudaGetSymbolAddress((void**)&psh2, g_sh2);

    const int SMEM = 768*4 + 2 * BUF_WRD * 4;    // 39936 B
    cudaFuncSetAttribute(gemm_mma<C2V, false, false, true>,
                         cudaFuncAttributeMaxDynamicSharedMemorySize, SMEM);
    cudaFuncSetAttribute(gemm_mma<C1V, false, true, false>,
                         cudaFuncAttributeMaxDynamicSharedMemorySize, SMEM);
    cudaFuncSetAttribute(gemm_mma<K2V, true, false, false>,
                         cudaFuncAttributeMaxDynamicSharedMemorySize, SMEM);

    // 1) 3-NN weights
    nn3_kernel<<<dim3(NPTS/256, BATCH), 256>>>(xyz1, xyz2);
    // 2) Z = P2 @ W1b^T -> fp16  (16384 x 256, K=256; W1b = w1[:,128:384])
    gemm_mma<C2V, false, false, true><<<dim3(N1V/128, (BATCH*SPTS)/128), 256, SMEM>>>(
        points2, C2V, w1 + C1V, K1V, nullptr, nullptr, nullptr, nullptr,
        pZh, nullptr, nullptr, N1V);
    // 3) Y1 = P1 @ W1a^T + interp(Zh) + b1 -> fp32  (K=128; interp fused)
    gemm_mma<C1V, false, true, false><<<dim3(N1V/128, MROWS/128), 256, SMEM>>>(
        points1, C1V, w1, K1V, b1, nullptr, nullptr, pZh,
        pY1, pps1, ppq1, N1V);
    bn_stats2<<<N1V, 128>>>(pps1, ppq1, g1, beta1, psc1, psh1);
    // 4) Y2 = relu(BN1(Y1)) @ W2^T + b2  (fp32 A path, unchanged from R15)
    gemm_mma<K2V, true, false, false><<<dim3(N2V/128, MROWS/128), 256, SMEM>>>(
        pY1, K2V, w2, K2V, b2, psc1, psh1, nullptr,
        pY2, pps2, ppq2, N2V);
    bn_stats2<<<N2V, 128>>>(pps2, ppq2, g2, beta2, psc2, psh2);
    // 5) out = relu(BN2(Y2))
    bn_relu_out_kernel<<<(MROWS * N2V / 4) / 256, 256>>>(pY2, out);
}